// round 10
// baseline (speedup 1.0000x reference)
#include <cuda_runtime.h>
#include <math.h>

#define Bz 32
#define Tz 256
#define Dz 768
#define Hz 512
#define Gz 2048   // 4*H
#define NCz 25
#define HCz 1024  // 2*H

// ---------------- scratch (static device globals; no allocs allowed) ----------------
static __device__ float g_xz[2][Tz][Bz][Gz];   // 128 MiB
static __device__ float g_h[Bz][Tz][HCz];      // 32 MiB
static __device__ float g_nll[Bz];
static __device__ unsigned g_bar[2][2][32];    // [dir][batch-group], 128B apart

// ---------------- f32x2 packed FMA helpers ----------------
__device__ __forceinline__ unsigned long long pk2(float a) {
    unsigned long long r;
    asm("mov.b64 %0, {%1, %1};" : "=l"(r) : "f"(a));
    return r;
}
__device__ __forceinline__ void fma2(unsigned long long& d, unsigned long long a, unsigned long long b) {
    asm("fma.rn.f32x2 %0, %1, %2, %0;" : "+l"(d) : "l"(a), "l"(b));
}
__device__ __forceinline__ void unpk(unsigned long long v, float& x, float& y) {
    asm("mov.b64 {%0, %1}, %2;" : "=f"(x), "=f"(y) : "l"(v));
}
__device__ __forceinline__ unsigned ld_acq(const unsigned* p) {
    unsigned v;
    asm volatile("ld.acquire.gpu.u32 %0, [%1];" : "=r"(v) : "l"(p));
    return v;
}
__device__ __forceinline__ float wsum(float v) {
    #pragma unroll
    for (int o = 16; o; o >>= 1) v += __shfl_xor_sync(0xffffffffu, v, o);
    return v;
}
__device__ __forceinline__ float wmax(float v) {
    #pragma unroll
    for (int o = 16; o; o >>= 1) v = fmaxf(v, __shfl_xor_sync(0xffffffffu, v, o));
    return v;
}
// fast activations (MUFU-based, ~1e-6 rel err)
__device__ __forceinline__ float fsig(float x) {
    return __fdividef(1.f, 1.f + __expf(-x));
}
__device__ __forceinline__ float ftanh(float x) {
    x = fminf(15.f, fmaxf(-15.f, x));
    float e = __expf(2.f * x);
    return __fdividef(e - 1.f, e + 1.f);
}

__global__ void k_init() {
    int t = threadIdx.x;
    if (t < 4) g_bar[t >> 1][t & 1][0] = 0;
}

// ---------------- input GEMM (double-buffered, 1 sync/tile) — R4 exact ----------------
__global__ __launch_bounds__(256) void k_gemm_xz(
    const float* __restrict__ emb,
    const float* __restrict__ kf, const float* __restrict__ bf,
    const float* __restrict__ kb, const float* __restrict__ bb)
{
    __shared__ __align__(16) float As[2][16][132];
    __shared__ __align__(16) float Bs[2][16][128];

    const int bm = blockIdx.y;
    const int n_base = blockIdx.x * 128;
    const int dir = n_base >> 11;
    const int colb = n_base & 2047;
    const float* __restrict__ W    = dir ? kb : kf;
    const float* __restrict__ bias = dir ? bb : bf;

    const int tid = threadIdx.x;
    const int tx = tid & 15, ty = tid >> 4;

    unsigned long long acc[8][4];
    #pragma unroll
    for (int i = 0; i < 8; i++)
        #pragma unroll
        for (int j = 0; j < 4; j++) acc[i][j] = 0ull;

    const int a_row = tid >> 2;            // 0..63
    const int a_k4  = (tid & 3) * 4;
    const int b_col = (tid & 31) * 4;
    const int b_kr  = tid >> 5;            // 0..7
    const float* Aptr = emb + (size_t)(bm * 128) * Dz;

    float4 pa0, pa1, pb0, pb1;
    pa0 = *(const float4*)(Aptr + (size_t)a_row * Dz + a_k4);
    pa1 = *(const float4*)(Aptr + (size_t)(a_row + 64) * Dz + a_k4);
    pb0 = *(const float4*)(W + (size_t)b_kr * Gz + colb + b_col);
    pb1 = *(const float4*)(W + (size_t)(b_kr + 8) * Gz + colb + b_col);

    int p = 0;
    for (int k0 = 0; k0 < Dz; k0 += 16) {
        As[p][a_k4 + 0][a_row] = pa0.x;
        As[p][a_k4 + 1][a_row] = pa0.y;
        As[p][a_k4 + 2][a_row] = pa0.z;
        As[p][a_k4 + 3][a_row] = pa0.w;
        As[p][a_k4 + 0][a_row + 64] = pa1.x;
        As[p][a_k4 + 1][a_row + 64] = pa1.y;
        As[p][a_k4 + 2][a_row + 64] = pa1.z;
        As[p][a_k4 + 3][a_row + 64] = pa1.w;
        *(float4*)&Bs[p][b_kr][b_col]     = pb0;
        *(float4*)&Bs[p][b_kr + 8][b_col] = pb1;
        __syncthreads();
        if (k0 + 16 < Dz) {
            int kn = k0 + 16;
            pa0 = *(const float4*)(Aptr + (size_t)a_row * Dz + kn + a_k4);
            pa1 = *(const float4*)(Aptr + (size_t)(a_row + 64) * Dz + kn + a_k4);
            pb0 = *(const float4*)(W + (size_t)(kn + b_kr) * Gz + colb + b_col);
            pb1 = *(const float4*)(W + (size_t)(kn + b_kr + 8) * Gz + colb + b_col);
        }
        #pragma unroll
        for (int kk = 0; kk < 16; kk++) {
            float4 a0 = *(const float4*)&As[p][kk][ty * 8];
            float4 a1 = *(const float4*)&As[p][kk][ty * 8 + 4];
            ulonglong2 br0 = *(const ulonglong2*)&Bs[p][kk][tx * 8];
            ulonglong2 br1 = *(const ulonglong2*)&Bs[p][kk][tx * 8 + 4];
            float am[8] = {a0.x, a0.y, a0.z, a0.w, a1.x, a1.y, a1.z, a1.w};
            #pragma unroll
            for (int m = 0; m < 8; m++) {
                unsigned long long a2 = pk2(am[m]);
                fma2(acc[m][0], a2, br0.x);
                fma2(acc[m][1], a2, br0.y);
                fma2(acc[m][2], a2, br1.x);
                fma2(acc[m][3], a2, br1.y);
            }
        }
        p ^= 1;
    }

    #pragma unroll
    for (int m = 0; m < 8; m++) {
        int row = bm * 128 + ty * 8 + m;
        int b = row >> 8, t = row & 255;
        #pragma unroll
        for (int j = 0; j < 4; j++) {
            float x, y;
            unpk(acc[m][j], x, y);
            int c = colb + tx * 8 + 2 * j;
            g_xz[dir][t][b][c]     = x + bias[c];
            g_xz[dir][t][b][c + 1] = y + bias[c + 1];
        }
    }
}

// ---------------- persistent BiLSTM recurrence: 2-group pipelined ----------------
// 128 CTAs: 64/dir, each owns 8 h-units (32 gate cols). Batches split into two
// groups of 16 with independent barriers; phase-interleaving hides each group's
// barrier latency + straggler skew under the other group's compute.
#define NCTA_DIR 64
#define UPC 8
#define GRP_B 16
#define HS_PAD 17
#define RSS 36
#define SM_REC (512 * 32)                 // 16384 floats
#define SM_HS  (8 * 64 * HS_PAD)          // 8704 floats
#define SM_RED (8 * GRP_B * RSS)          // 4608 floats

__global__ __launch_bounds__(256, 1) void k_lstm(
    const float* __restrict__ rf, const float* __restrict__ rb)
{
    extern __shared__ float sm[];
    float* rec_s = sm;                    // [k*32 + c]
    float* h_s   = sm + SM_REC;           // per-warp [64][HS_PAD]
    float* red   = sm + SM_REC + SM_HS;   // [w][GRP_B][RSS]

    const int cta = blockIdx.x;
    const int dir = cta >> 6;
    const int cd  = cta & 63;
    const int u0  = cd * UPC;
    const float* __restrict__ R = dir ? rb : rf;
    const int tid = threadIdx.x;

    for (int i = tid; i < 512 * 32; i += 256) {
        int k = i >> 5, c = i & 31;
        int g = c >> 3, u = c & 7;
        rec_s[i] = R[(size_t)k * Gz + g * 512 + u0 + u];
    }

    const int w    = tid >> 5;
    const int lane = tid & 31;
    const int b0l  = (lane >> 2) * 2;     // local batch pair 0,2,..,14
    const int c0   = (lane & 3) * 8;
    const int kbase = w * 64;
    float* hw = h_s + w * 64 * HS_PAD;
    float* rw = red + w * GRP_B * RSS;

    const int gbl = tid >> 3;             // gate: local batch 0..15 (tid<128)
    const int gu  = tid & 7;              // gate: unit 0..7
    float cst[2] = {0.f, 0.f};

    const float* ghf = (const float*)g_h;

    __syncthreads();

    for (int step = 0; step < Tz; step++) {
        const int tcur = dir ? (Tz - 1 - step) : step;

        #pragma unroll
        for (int grp = 0; grp < 2; grp++) {
            const int gb0 = grp * GRP_B;

            // xz prefetch for this phase (overlaps wait + fma)
            float zx[4];
            if (tid < 128) {
                #pragma unroll
                for (int g = 0; g < 4; g++)
                    zx[g] = g_xz[dir][tcur][gb0 + gbl][g * 512 + u0 + gu];
            }

            if (step > 0) {
                // wait: other CTAs' arrivals for this group's step-1 were issued
                // a full phase ago — usually already satisfied.
                if (tid == 0) {
                    const unsigned target = (unsigned)(NCTA_DIR * step);
                    while (ld_acq(&g_bar[dir][grp][0]) < target) { }
                }
                __syncthreads();

                const int tprev = dir ? (tcur + 1) : (tcur - 1);
                // per-warp staging of this warp's K-slice for this batch group
                const float* hsrc = ghf + (size_t)tprev * HCz + dir * 512 + kbase + lane * 2;
                #pragma unroll 8
                for (int bi = 0; bi < GRP_B; bi++) {
                    float2 v = *(const float2*)(hsrc + (size_t)(gb0 + bi) * Tz * HCz);
                    hw[(lane * 2) * HS_PAD + bi]     = v.x;
                    hw[(lane * 2 + 1) * HS_PAD + bi] = v.y;
                }
                __syncwarp();

                unsigned long long acc[2][4];
                #pragma unroll
                for (int m = 0; m < 2; m++)
                    #pragma unroll
                    for (int q = 0; q < 4; q++) acc[m][q] = 0ull;

                #pragma unroll 4
                for (int kk = 0; kk < 64; kk++) {
                    const float* hr = &hw[kk * HS_PAD + b0l];
                    float h0 = hr[0], h1 = hr[1];
                    ulonglong2 r0 = *(const ulonglong2*)&rec_s[(kbase + kk) * 32 + c0];
                    ulonglong2 r1 = *(const ulonglong2*)&rec_s[(kbase + kk) * 32 + c0 + 4];
                    unsigned long long a;
                    a = pk2(h0); fma2(acc[0][0], a, r0.x); fma2(acc[0][1], a, r0.y); fma2(acc[0][2], a, r1.x); fma2(acc[0][3], a, r1.y);
                    a = pk2(h1); fma2(acc[1][0], a, r0.x); fma2(acc[1][1], a, r0.y); fma2(acc[1][2], a, r1.x); fma2(acc[1][3], a, r1.y);
                }
                #pragma unroll
                for (int m = 0; m < 2; m++) {
                    #pragma unroll
                    for (int q = 0; q < 4; q++) {
                        float x, y;
                        unpk(acc[m][q], x, y);
                        rw[(b0l + m) * RSS + c0 + 2 * q]     = x;
                        rw[(b0l + m) * RSS + c0 + 2 * q + 1] = y;
                    }
                }
                __syncthreads();   // red[] ready for gate readers
            }

            // gate phase: one thread per (batch-in-group, unit)
            if (tid < 128) {
                float z[4];
                #pragma unroll
                for (int g = 0; g < 4; g++) {
                    float s = zx[g];
                    if (step > 0) {
                        #pragma unroll
                        for (int w2 = 0; w2 < 8; w2++)
                            s += red[w2 * GRP_B * RSS + gbl * RSS + g * 8 + gu];
                    }
                    z[g] = s;
                }
                float ig = fsig(z[0]);
                float fg = fsig(z[1]);
                float og = fsig(z[3]);
                float c2 = fg * cst[grp] + ig * ftanh(z[2]);
                cst[grp] = c2;
                float hval = og * ftanh(c2);
                g_h[gb0 + gbl][tcur][dir * 512 + u0 + gu] = hval;
            }

            // arrive: h stores for this group complete, publish one arrival
            __syncthreads();
            if (tid == 0) {
                __threadfence();
                atomicAdd(&g_bar[dir][grp][0], 1u);
            }
        }
    }
}

// ---------------- dense + SELU (R4 exact) ----------------
#define DW_STRIDE 1026
#define DSM_W 25664
#define DSM_H (8 * 2048)

__global__ __launch_bounds__(256, 1) void k_dense(
    const float* __restrict__ W, const float* __restrict__ bias,
    float* __restrict__ out, int loff)
{
    extern __shared__ float sm[];
    float* sw = sm;
    float* sh = sm + DSM_W;

    const int tid = threadIdx.x;
    for (int i = tid; i < HCz * NCz; i += 256) {
        int k = i / NCz, n = i - k * NCz;
        sw[n * DW_STRIDE + k] = W[i];
    }
    __syncthreads();

    const int w = tid >> 5, lane = tid & 31;
    const int gw = blockIdx.x * 8 + w;
    float* hh = sh + w * 2048;
    const float* ghf = (const float*)g_h;

    const float SC = 1.0507009873554804934193f;
    const float AL = 1.6732632423543772848170f;
    float bn = (lane < NCz) ? bias[lane] : 0.f;

    for (int base = gw * 2; base < Bz * Tz; base += 1184 * 2) {
        const float4* s0 = (const float4*)(ghf + (size_t)base * HCz);
        const float4* s1 = (const float4*)(ghf + (size_t)(base + 1) * HCz);
        float4* d0 = (float4*)hh;
        float4* d1 = (float4*)(hh + 1024);
        #pragma unroll
        for (int j = 0; j < 8; j++) {
            d0[j * 32 + lane] = s0[j * 32 + lane];
            d1[j * 32 + lane] = s1[j * 32 + lane];
        }
        __syncwarp();

        if (lane < NCz) {
            unsigned long long acc0 = 0ull, acc1 = 0ull;
            const float* wn = sw + lane * DW_STRIDE;
            #pragma unroll 8
            for (int k = 0; k < HCz; k += 2) {
                unsigned long long wv = *(const unsigned long long*)&wn[k];
                unsigned long long h0 = *(const unsigned long long*)&hh[k];
                unsigned long long h1 = *(const unsigned long long*)&hh[1024 + k];
                fma2(acc0, h0, wv);
                fma2(acc1, h1, wv);
            }
            float x0, y0, x1, y1;
            unpk(acc0, x0, y0);
            unpk(acc1, x1, y1);
            float v0 = x0 + y0 + bn;
            float v1 = x1 + y1 + bn;
            v0 = v0 > 0.f ? SC * v0 : SC * AL * (expf(v0) - 1.f);
            v1 = v1 > 0.f ? SC * v1 : SC * AL * (expf(v1) - 1.f);
            out[loff + (size_t)base * NCz + lane]       = v0;
            out[loff + (size_t)(base + 1) * NCz + lane] = v1;
        }
        __syncwarp();
    }
}

// ---------------- CRF NLL (one warp per batch element) ----------------
__global__ void k_crf(const float* __restrict__ logits,
                      const int* __restrict__ tags,
                      const int* __restrict__ seq_lens,
                      const float* __restrict__ trans)
{
    __shared__ float Ts[NCz * NCz];
    __shared__ float alpha[NCz];
    const int b = blockIdx.x;
    const int lane = threadIdx.x;

    for (int i = lane; i < NCz * NCz; i += 32) Ts[i] = trans[i];
    __syncwarp();

    int len = seq_lens[b];
    if (len < 1) len = 1;
    if (len > Tz) len = Tz;

    const float* __restrict__ L = logits + (size_t)b * Tz * NCz;
    const int* __restrict__ tg = tags + (size_t)b * Tz;

    float us = 0.f, bs = 0.f;
    for (int t = lane; t < len; t += 32) {
        us += L[t * NCz + tg[t]];
        if (t >= 1) bs += Ts[tg[t - 1] * NCz + tg[t]];
    }
    us = wsum(us);
    bs = wsum(bs);

    if (lane < NCz) alpha[lane] = L[lane];
    __syncwarp();
    for (int t = 1; t < len; t++) {
        float v = 0.f;
        if (lane < NCz) {
            float m = -1e30f;
            for (int i = 0; i < NCz; i++) m = fmaxf(m, alpha[i] + Ts[i * NCz + lane]);
            float s = 0.f;
            for (int i = 0; i < NCz; i++) s += expf(alpha[i] + Ts[i * NCz + lane] - m);
            v = m + logf(s) + L[t * NCz + lane];
        }
        __syncwarp();
        if (lane < NCz) alpha[lane] = v;
        __syncwarp();
    }
    float a = (lane < NCz) ? alpha[lane] : -1e30f;
    float m = wmax(a);
    float s = wsum((lane < NCz) ? expf(a - m) : 0.f);
    float logz = m + logf(s);
    if (lane == 0) g_nll[b] = -(us + bs - logz);
}

__global__ void k_loss(float* __restrict__ out, int loff) {
    float v = (threadIdx.x < Bz) ? g_nll[threadIdx.x] : 0.f;
    v = wsum(v);
    if (threadIdx.x == 0 && loff >= 1) out[0] = v / (float)Bz;
}

// ---------------- launch (single stream, sequential — known-safe) ----------------
extern "C" void kernel_launch(void* const* d_in, const int* in_sizes, int n_in,
                              void* d_out, int out_size)
{
    const float* emb     = (const float*)d_in[0];
    const int*   targets = (const int*)d_in[1];
    const int*   seqlens = (const int*)d_in[2];
    const float* k_fwd   = (const float*)d_in[3];
    const float* r_fwd   = (const float*)d_in[4];
    const float* b_fwd   = (const float*)d_in[5];
    const float* k_bwd   = (const float*)d_in[6];
    const float* r_bwd   = (const float*)d_in[7];
    const float* b_bwd   = (const float*)d_in[8];
    const float* dense_w = (const float*)d_in[9];
    const float* dense_b = (const float*)d_in[10];
    const float* trans   = (const float*)d_in[11];
    float* out = (float*)d_out;

    int loff = out_size - Bz * Tz * NCz;
    if (loff < 0) loff = 0;

    const int smem_lstm  = (SM_REC + SM_HS + SM_RED) * (int)sizeof(float);  // 118784
    const int smem_dense = (DSM_W + DSM_H) * (int)sizeof(float);            // 168192
    cudaFuncSetAttribute(k_lstm, cudaFuncAttributeMaxDynamicSharedMemorySize, smem_lstm);
    cudaFuncSetAttribute(k_dense, cudaFuncAttributeMaxDynamicSharedMemorySize, smem_dense);

    k_init<<<1, 32>>>();
    dim3 ggrid(32, 64);
    k_gemm_xz<<<ggrid, 256>>>(emb, k_fwd, b_fwd, k_bwd, b_bwd);
    k_lstm<<<2 * NCTA_DIR, 256, smem_lstm>>>(r_fwd, r_bwd);
    k_dense<<<148, 256, smem_dense>>>(dense_w, dense_b, out, loff);
    k_crf<<<32, 32>>>(out + loff, targets, seqlens, trans);
    k_loss<<<1, 32>>>(out, loff);
}

// round 11
// speedup vs baseline: 1.2917x; 1.2917x over previous
#include <cuda_runtime.h>
#include <math.h>

#define Bz 32
#define Tz 256
#define Dz 768
#define Hz 512
#define Gz 2048   // 4*H
#define NCz 25
#define HCz 1024  // 2*H

// ---------------- scratch (static device globals; no allocs allowed) ----------------
static __device__ float g_xz[2][Tz][Bz][Gz];   // 128 MiB
static __device__ float g_h[Bz][Tz][HCz];      // 32 MiB
static __device__ float g_nll[Bz];
static __device__ unsigned g_bar[2];
static __device__ int g_pad_sink;

// ---------------- f32x2 packed FMA helpers ----------------
__device__ __forceinline__ unsigned long long pk2(float a) {
    unsigned long long r;
    asm("mov.b64 %0, {%1, %1};" : "=l"(r) : "f"(a));
    return r;
}
__device__ __forceinline__ void fma2(unsigned long long& d, unsigned long long a, unsigned long long b) {
    asm("fma.rn.f32x2 %0, %1, %2, %0;" : "+l"(d) : "l"(a), "l"(b));
}
__device__ __forceinline__ void unpk(unsigned long long v, float& x, float& y) {
    asm("mov.b64 {%0, %1}, %2;" : "=f"(x), "=f"(y) : "l"(v));
}
__device__ __forceinline__ unsigned ld_acq(const unsigned* p) {
    unsigned v;
    asm volatile("ld.acquire.gpu.u32 %0, [%1];" : "=r"(v) : "l"(p));
    return v;
}
__device__ __forceinline__ float wsum(float v) {
    #pragma unroll
    for (int o = 16; o; o >>= 1) v += __shfl_xor_sync(0xffffffffu, v, o);
    return v;
}
__device__ __forceinline__ float wmax(float v) {
    #pragma unroll
    for (int o = 16; o; o >>= 1) v = fmaxf(v, __shfl_xor_sync(0xffffffffu, v, o));
    return v;
}
// fast activations (MUFU-based, ~1e-6 rel err)
__device__ __forceinline__ float fsig(float x) {
    return __fdividef(1.f, 1.f + __expf(-x));
}
__device__ __forceinline__ float ftanh(float x) {
    x = fminf(15.f, fmaxf(-15.f, x));
    float e = __expf(2.f * x);
    return __fdividef(e - 1.f, e + 1.f);
}

__global__ void k_init() { g_bar[0] = 0; g_bar[1] = 0; }

// tiny pad kernel: shifts the ncu sample slot so k_lstm gets profiled
__global__ void k_pad() { if (threadIdx.x == 1000000) g_pad_sink = 1; }

// ---------------- input GEMM (double-buffered, 1 sync/tile) ----------------
// M=8192, N=4096 (dir*2048+c), K=768. Tile 128x128, BK=16, 256 thr, 8x8/thread.
__global__ __launch_bounds__(256) void k_gemm_xz(
    const float* __restrict__ emb,
    const float* __restrict__ kf, const float* __restrict__ bf,
    const float* __restrict__ kb, const float* __restrict__ bb)
{
    __shared__ __align__(16) float As[2][16][132];
    __shared__ __align__(16) float Bs[2][16][128];

    const int bm = blockIdx.y;
    const int n_base = blockIdx.x * 128;
    const int dir = n_base >> 11;
    const int colb = n_base & 2047;
    const float* __restrict__ W    = dir ? kb : kf;
    const float* __restrict__ bias = dir ? bb : bf;

    const int tid = threadIdx.x;
    const int tx = tid & 15, ty = tid >> 4;

    unsigned long long acc[8][4];
    #pragma unroll
    for (int i = 0; i < 8; i++)
        #pragma unroll
        for (int j = 0; j < 4; j++) acc[i][j] = 0ull;

    const int a_row = tid >> 2;            // 0..63
    const int a_k4  = (tid & 3) * 4;
    const int b_col = (tid & 31) * 4;
    const int b_kr  = tid >> 5;            // 0..7
    const float* Aptr = emb + (size_t)(bm * 128) * Dz;

    float4 pa0, pa1, pb0, pb1;
    pa0 = *(const float4*)(Aptr + (size_t)a_row * Dz + a_k4);
    pa1 = *(const float4*)(Aptr + (size_t)(a_row + 64) * Dz + a_k4);
    pb0 = *(const float4*)(W + (size_t)b_kr * Gz + colb + b_col);
    pb1 = *(const float4*)(W + (size_t)(b_kr + 8) * Gz + colb + b_col);

    int p = 0;
    for (int k0 = 0; k0 < Dz; k0 += 16) {
        As[p][a_k4 + 0][a_row] = pa0.x;
        As[p][a_k4 + 1][a_row] = pa0.y;
        As[p][a_k4 + 2][a_row] = pa0.z;
        As[p][a_k4 + 3][a_row] = pa0.w;
        As[p][a_k4 + 0][a_row + 64] = pa1.x;
        As[p][a_k4 + 1][a_row + 64] = pa1.y;
        As[p][a_k4 + 2][a_row + 64] = pa1.z;
        As[p][a_k4 + 3][a_row + 64] = pa1.w;
        *(float4*)&Bs[p][b_kr][b_col]     = pb0;
        *(float4*)&Bs[p][b_kr + 8][b_col] = pb1;
        __syncthreads();
        if (k0 + 16 < Dz) {
            int kn = k0 + 16;
            pa0 = *(const float4*)(Aptr + (size_t)a_row * Dz + kn + a_k4);
            pa1 = *(const float4*)(Aptr + (size_t)(a_row + 64) * Dz + kn + a_k4);
            pb0 = *(const float4*)(W + (size_t)(kn + b_kr) * Gz + colb + b_col);
            pb1 = *(const float4*)(W + (size_t)(kn + b_kr + 8) * Gz + colb + b_col);
        }
        #pragma unroll
        for (int kk = 0; kk < 16; kk++) {
            float4 a0 = *(const float4*)&As[p][kk][ty * 8];
            float4 a1 = *(const float4*)&As[p][kk][ty * 8 + 4];
            ulonglong2 br0 = *(const ulonglong2*)&Bs[p][kk][tx * 8];
            ulonglong2 br1 = *(const ulonglong2*)&Bs[p][kk][tx * 8 + 4];
            float am[8] = {a0.x, a0.y, a0.z, a0.w, a1.x, a1.y, a1.z, a1.w};
            #pragma unroll
            for (int m = 0; m < 8; m++) {
                unsigned long long a2 = pk2(am[m]);
                fma2(acc[m][0], a2, br0.x);
                fma2(acc[m][1], a2, br0.y);
                fma2(acc[m][2], a2, br1.x);
                fma2(acc[m][3], a2, br1.y);
            }
        }
        p ^= 1;
    }

    #pragma unroll
    for (int m = 0; m < 8; m++) {
        int row = bm * 128 + ty * 8 + m;
        int b = row >> 8, t = row & 255;
        #pragma unroll
        for (int j = 0; j < 4; j++) {
            float x, y;
            unpk(acc[m][j], x, y);
            int c = colb + tx * 8 + 2 * j;
            g_xz[dir][t][b][c]     = x + bias[c];
            g_xz[dir][t][b][c + 1] = y + bias[c + 1];
        }
    }
}

// ---------------- persistent BiLSTM recurrence (the 3108-us configuration) ----------------
#define NCTA_DIR 64
#define UPC 8
#define HS_PAD 33
#define RED_STRIDE 40
#define SM_REC (512 * 32)                 // 16384 floats
#define SM_HS  (8 * 64 * HS_PAD)          // 16896 floats
#define SM_RED (8 * 32 * RED_STRIDE)      // 10240 floats

__global__ __launch_bounds__(256, 1) void k_lstm(
    const float* __restrict__ rf, const float* __restrict__ rb)
{
    extern __shared__ float sm[];
    float* rec_s = sm;                    // [k*32 + c]
    float* h_s   = sm + SM_REC;           // per-warp [64][HS_PAD]
    float* red   = sm + SM_REC + SM_HS;   // [w][32][RED_STRIDE]

    const int cta = blockIdx.x;
    const int dir = cta >> 6;
    const int cd  = cta & 63;
    const int u0  = cd * UPC;
    const float* __restrict__ R = dir ? rb : rf;
    const int tid = threadIdx.x;

    for (int i = tid; i < 512 * 32; i += 256) {
        int k = i >> 5, c = i & 31;
        int g = c >> 3, u = c & 7;
        rec_s[i] = R[(size_t)k * Gz + g * 512 + u0 + u];
    }

    const int w    = tid >> 5;
    const int lane = tid & 31;
    const int bb   = lane >> 2;
    const int cc   = lane & 3;
    const int b0   = bb * 4, c0 = cc * 8;
    const int kbase = w * 64;
    float* hw = h_s + w * 64 * HS_PAD;
    float* rw = red + w * 32 * RED_STRIDE;

    const int gb = tid >> 3;              // gate-phase batch 0..31
    const int gu = tid & 7;               // gate-phase unit 0..7
    float cstate = 0.f;

    const float* ghf = (const float*)g_h;

    __syncthreads();

    for (int step = 0; step < Tz; step++) {
        const int tcur = dir ? (Tz - 1 - step) : step;

        // prefetch gate pre-activations (hidden behind the fma phase)
        float zx[4];
        #pragma unroll
        for (int g = 0; g < 4; g++)
            zx[g] = g_xz[dir][tcur][gb][g * 512 + u0 + gu];

        if (step > 0) {
            const int tprev = dir ? (tcur + 1) : (tcur - 1);
            // per-warp staging of this warp's K-slice of h (transposed)
            const float* hsrc = ghf + (size_t)tprev * HCz + dir * 512 + kbase + lane * 2;
            #pragma unroll 8
            for (int bi = 0; bi < 32; bi++) {
                float2 v = *(const float2*)(hsrc + (size_t)bi * Tz * HCz);
                hw[(lane * 2) * HS_PAD + bi]     = v.x;
                hw[(lane * 2 + 1) * HS_PAD + bi] = v.y;
            }
            __syncwarp();

            unsigned long long acc[4][4];
            #pragma unroll
            for (int m = 0; m < 4; m++)
                #pragma unroll
                for (int q = 0; q < 4; q++) acc[m][q] = 0ull;

            #pragma unroll 4
            for (int kk = 0; kk < 64; kk++) {
                const float* hr = &hw[kk * HS_PAD + b0];
                float h0 = hr[0], h1 = hr[1], h2 = hr[2], h3 = hr[3];
                ulonglong2 r0 = *(const ulonglong2*)&rec_s[(kbase + kk) * 32 + c0];
                ulonglong2 r1 = *(const ulonglong2*)&rec_s[(kbase + kk) * 32 + c0 + 4];
                unsigned long long a;
                a = pk2(h0); fma2(acc[0][0], a, r0.x); fma2(acc[0][1], a, r0.y); fma2(acc[0][2], a, r1.x); fma2(acc[0][3], a, r1.y);
                a = pk2(h1); fma2(acc[1][0], a, r0.x); fma2(acc[1][1], a, r0.y); fma2(acc[1][2], a, r1.x); fma2(acc[1][3], a, r1.y);
                a = pk2(h2); fma2(acc[2][0], a, r0.x); fma2(acc[2][1], a, r0.y); fma2(acc[2][2], a, r1.x); fma2(acc[2][3], a, r1.y);
                a = pk2(h3); fma2(acc[3][0], a, r0.x); fma2(acc[3][1], a, r0.y); fma2(acc[3][2], a, r1.x); fma2(acc[3][3], a, r1.y);
            }
            #pragma unroll
            for (int m = 0; m < 4; m++) {
                #pragma unroll
                for (int q = 0; q < 4; q++) {
                    float x, y;
                    unpk(acc[m][q], x, y);
                    rw[(b0 + m) * RED_STRIDE + c0 + 2 * q]     = x;
                    rw[(b0 + m) * RED_STRIDE + c0 + 2 * q + 1] = y;
                }
            }
            __syncthreads();
        }

        // gate phase
        float z[4];
        #pragma unroll
        for (int g = 0; g < 4; g++) {
            float s = zx[g];
            if (step > 0) {
                #pragma unroll
                for (int w2 = 0; w2 < 8; w2++)
                    s += red[w2 * 32 * RED_STRIDE + gb * RED_STRIDE + g * 8 + gu];
            }
            z[g] = s;
        }
        float ig = fsig(z[0]);
        float fg = fsig(z[1]);
        float og = fsig(z[3]);
        cstate = fg * cstate + ig * ftanh(z[2]);
        float hval = og * ftanh(cstate);
        g_h[gb][tcur][dir * 512 + u0 + gu] = hval;

        __syncthreads();
        if (tid == 0) {
            __threadfence();
            atomicAdd(&g_bar[dir], 1u);
            unsigned target = (unsigned)(NCTA_DIR * (step + 1));
            while (ld_acq(&g_bar[dir]) < target) { }
        }
        __syncthreads();
    }
}

// ---------------- dense + SELU ----------------
#define DW_STRIDE 1026
#define DSM_W 25664                       // 25*1026=25650 padded to multiple of 16 floats
#define DSM_H (8 * 2048)                  // 16384 floats

__global__ __launch_bounds__(256, 1) void k_dense(
    const float* __restrict__ W, const float* __restrict__ bias,
    float* __restrict__ out, int loff)
{
    extern __shared__ float sm[];
    float* sw = sm;               // [n*DW_STRIDE + k]
    float* sh = sm + DSM_W;       // per-warp 2 rows of h (16B-aligned)

    const int tid = threadIdx.x;
    for (int i = tid; i < HCz * NCz; i += 256) {
        int k = i / NCz, n = i - k * NCz;
        sw[n * DW_STRIDE + k] = W[i];
    }
    __syncthreads();

    const int w = tid >> 5, lane = tid & 31;
    const int gw = blockIdx.x * 8 + w;     // 0..1183
    float* hh = sh + w * 2048;
    const float* ghf = (const float*)g_h;

    const float SC = 1.0507009873554804934193f;
    const float AL = 1.6732632423543772848170f;
    float bn = (lane < NCz) ? bias[lane] : 0.f;

    for (int base = gw * 2; base < Bz * Tz; base += 1184 * 2) {
        const float4* s0 = (const float4*)(ghf + (size_t)base * HCz);
        const float4* s1 = (const float4*)(ghf + (size_t)(base + 1) * HCz);
        float4* d0 = (float4*)hh;
        float4* d1 = (float4*)(hh + 1024);
        #pragma unroll
        for (int j = 0; j < 8; j++) {
            d0[j * 32 + lane] = s0[j * 32 + lane];
            d1[j * 32 + lane] = s1[j * 32 + lane];
        }
        __syncwarp();

        if (lane < NCz) {
            unsigned long long acc0 = 0ull, acc1 = 0ull;
            const float* wn = sw + lane * DW_STRIDE;
            #pragma unroll 8
            for (int k = 0; k < HCz; k += 2) {
                unsigned long long wv = *(const unsigned long long*)&wn[k];
                unsigned long long h0 = *(const unsigned long long*)&hh[k];
                unsigned long long h1 = *(const unsigned long long*)&hh[1024 + k];
                fma2(acc0, h0, wv);
                fma2(acc1, h1, wv);
            }
            float x0, y0, x1, y1;
            unpk(acc0, x0, y0);
            unpk(acc1, x1, y1);
            float v0 = x0 + y0 + bn;
            float v1 = x1 + y1 + bn;
            v0 = v0 > 0.f ? SC * v0 : SC * AL * (expf(v0) - 1.f);
            v1 = v1 > 0.f ? SC * v1 : SC * AL * (expf(v1) - 1.f);
            out[loff + (size_t)base * NCz + lane]       = v0;
            out[loff + (size_t)(base + 1) * NCz + lane] = v1;
        }
        __syncwarp();
    }
}

// ---------------- CRF NLL (one warp per batch element) ----------------
__global__ void k_crf(const float* __restrict__ logits,
                      const int* __restrict__ tags,
                      const int* __restrict__ seq_lens,
                      const float* __restrict__ trans)
{
    __shared__ float Ts[NCz * NCz];
    __shared__ float alpha[NCz];
    const int b = blockIdx.x;
    const int lane = threadIdx.x;

    for (int i = lane; i < NCz * NCz; i += 32) Ts[i] = trans[i];
    __syncwarp();

    int len = seq_lens[b];
    if (len < 1) len = 1;
    if (len > Tz) len = Tz;

    const float* __restrict__ L = logits + (size_t)b * Tz * NCz;
    const int* __restrict__ tg = tags + (size_t)b * Tz;

    float us = 0.f, bs = 0.f;
    for (int t = lane; t < len; t += 32) {
        us += L[t * NCz + tg[t]];
        if (t >= 1) bs += Ts[tg[t - 1] * NCz + tg[t]];
    }
    us = wsum(us);
    bs = wsum(bs);

    if (lane < NCz) alpha[lane] = L[lane];
    __syncwarp();
    for (int t = 1; t < len; t++) {
        float v = 0.f;
        if (lane < NCz) {
            float m = -1e30f;
            for (int i = 0; i < NCz; i++) m = fmaxf(m, alpha[i] + Ts[i * NCz + lane]);
            float s = 0.f;
            for (int i = 0; i < NCz; i++) s += expf(alpha[i] + Ts[i * NCz + lane] - m);
            v = m + logf(s) + L[t * NCz + lane];
        }
        __syncwarp();
        if (lane < NCz) alpha[lane] = v;
        __syncwarp();
    }
    float a = (lane < NCz) ? alpha[lane] : -1e30f;
    float m = wmax(a);
    float s = wsum((lane < NCz) ? expf(a - m) : 0.f);
    float logz = m + logf(s);
    if (lane == 0) g_nll[b] = -(us + bs - logz);
}

__global__ void k_loss(float* __restrict__ out, int loff) {
    float v = (threadIdx.x < Bz) ? g_nll[threadIdx.x] : 0.f;
    v = wsum(v);
    if (threadIdx.x == 0 && loff >= 1) out[0] = v / (float)Bz;
}

// ---------------- launch ----------------
extern "C" void kernel_launch(void* const* d_in, const int* in_sizes, int n_in,
                              void* d_out, int out_size)
{
    const float* emb     = (const float*)d_in[0];
    const int*   targets = (const int*)d_in[1];
    const int*   seqlens = (const int*)d_in[2];
    const float* k_fwd   = (const float*)d_in[3];
    const float* r_fwd   = (const float*)d_in[4];
    const float* b_fwd   = (const float*)d_in[5];
    const float* k_bwd   = (const float*)d_in[6];
    const float* r_bwd   = (const float*)d_in[7];
    const float* b_bwd   = (const float*)d_in[8];
    const float* dense_w = (const float*)d_in[9];
    const float* dense_b = (const float*)d_in[10];
    const float* trans   = (const float*)d_in[11];
    float* out = (float*)d_out;

    int loff = out_size - Bz * Tz * NCz;
    if (loff < 0) loff = 0;

    const int smem_lstm  = (SM_REC + SM_HS + SM_RED) * (int)sizeof(float);  // 174080
    const int smem_dense = (DSM_W + DSM_H) * (int)sizeof(float);            // 168192
    cudaFuncSetAttribute(k_lstm, cudaFuncAttributeMaxDynamicSharedMemorySize, smem_lstm);
    cudaFuncSetAttribute(k_dense, cudaFuncAttributeMaxDynamicSharedMemorySize, smem_dense);

    k_init<<<1, 1>>>();
    dim3 ggrid(32, 64);
    k_gemm_xz<<<ggrid, 256>>>(emb, k_fwd, b_fwd, k_bwd, b_bwd);
    k_pad<<<1, 32>>>();   // shifts ncu's fixed sample slot onto k_lstm
    k_lstm<<<2 * NCTA_DIR, 256, smem_lstm>>>(r_fwd, r_bwd);
    k_dense<<<148, 256, smem_dense>>>(dense_w, dense_b, out, loff);
    k_crf<<<32, 32>>>(out + loff, targets, seqlens, trans);
    k_loss<<<1, 32>>>(out, loff);
}

// round 12
// speedup vs baseline: 1.6446x; 1.2732x over previous
#include <cuda_runtime.h>
#include <math.h>

#define Bz 32
#define Tz 256
#define Dz 768
#define Hz 512
#define Gz 2048   // 4*H
#define NCz 25
#define HCz 1024  // 2*H

// ---------------- scratch (static device globals; no allocs allowed) ----------------
static __device__ float g_xz[2][Tz][Bz][Gz];   // 128 MiB
static __device__ float g_h[Bz][Tz][HCz];      // 32 MiB
static __device__ float g_nll[Bz];
static __device__ unsigned g_bar[2];
static __device__ int g_pad_sink;

// ---------------- f32x2 packed FMA helpers ----------------
__device__ __forceinline__ unsigned long long pk2(float a) {
    unsigned long long r;
    asm("mov.b64 %0, {%1, %1};" : "=l"(r) : "f"(a));
    return r;
}
__device__ __forceinline__ void fma2(unsigned long long& d, unsigned long long a, unsigned long long b) {
    asm("fma.rn.f32x2 %0, %1, %2, %0;" : "+l"(d) : "l"(a), "l"(b));
}
__device__ __forceinline__ void unpk(unsigned long long v, float& x, float& y) {
    asm("mov.b64 {%0, %1}, %2;" : "=f"(x), "=f"(y) : "l"(v));
}
__device__ __forceinline__ unsigned ld_acq(const unsigned* p) {
    unsigned v;
    asm volatile("ld.acquire.gpu.u32 %0, [%1];" : "=r"(v) : "l"(p));
    return v;
}
__device__ __forceinline__ float wsum(float v) {
    #pragma unroll
    for (int o = 16; o; o >>= 1) v += __shfl_xor_sync(0xffffffffu, v, o);
    return v;
}
__device__ __forceinline__ float wmax(float v) {
    #pragma unroll
    for (int o = 16; o; o >>= 1) v = fmaxf(v, __shfl_xor_sync(0xffffffffu, v, o));
    return v;
}
// fast activations (MUFU-based, ~1e-6 rel err)
__device__ __forceinline__ float fsig(float x) {
    return __fdividef(1.f, 1.f + __expf(-x));
}
__device__ __forceinline__ float ftanh(float x) {
    x = fminf(15.f, fmaxf(-15.f, x));
    float e = __expf(2.f * x);
    return __fdividef(e - 1.f, e + 1.f);
}
// tf32 round-to-nearest (for tensor-core GEMM inputs)
__device__ __forceinline__ float tf32r(float x) {
    unsigned u;
    asm("cvt.rna.tf32.f32 %0, %1;" : "=r"(u) : "f"(x));
    return __uint_as_float(u);
}
// m16n8k8 tf32 MMA, fp32 accumulate
__device__ __forceinline__ void mma_tf32(float* c,
                                         unsigned a0, unsigned a1, unsigned a2, unsigned a3,
                                         unsigned b0, unsigned b1) {
    asm("mma.sync.aligned.m16n8k8.row.col.f32.tf32.tf32.f32 "
        "{%0,%1,%2,%3}, {%4,%5,%6,%7}, {%8,%9}, {%0,%1,%2,%3};"
        : "+f"(c[0]), "+f"(c[1]), "+f"(c[2]), "+f"(c[3])
        : "r"(a0), "r"(a1), "r"(a2), "r"(a3), "r"(b0), "r"(b1));
}

__global__ void k_init() { g_bar[0] = 0; g_bar[1] = 0; }

// tiny pad kernel: keeps ncu's fixed sample slot on k_lstm
__global__ void k_pad() { if (threadIdx.x == 1000000) g_pad_sink = 1; }

// ---------------- input GEMM: tf32 tensor-core version ----------------
// M=8192, N=4096 (dir*2048+c), K=768. Tile 128x128, BK=16, 256 thr (8 warps),
// warp tile 64x32, m16n8k8 fragments hand-loaded from smem, fp32 accumulators.
__global__ __launch_bounds__(256) void k_gemm_xz(
    const float* __restrict__ emb,
    const float* __restrict__ kf, const float* __restrict__ bf,
    const float* __restrict__ kb, const float* __restrict__ bb)
{
    __shared__ __align__(16) float As[2][16][132];   // [k][m], tf32-rounded
    __shared__ __align__(16) float Bs[2][16][132];   // [k][n], tf32-rounded

    const int bm = blockIdx.y;
    const int n_base = blockIdx.x * 128;
    const int dir = n_base >> 11;
    const int colb = n_base & 2047;
    const float* __restrict__ W    = dir ? kb : kf;
    const float* __restrict__ bias = dir ? bb : bf;

    const int tid  = threadIdx.x;
    const int warp = tid >> 5, lane = tid & 31;
    const int g    = lane >> 2, tig = lane & 3;     // quad-group layout
    const int mb   = (warp >> 2) * 64;              // warp m-offset (2 warps in m)
    const int nb   = (warp & 3) * 32;               // warp n-offset (4 warps in n)

    float c[4][4][4];
    #pragma unroll
    for (int mf = 0; mf < 4; mf++)
        #pragma unroll
        for (int nf = 0; nf < 4; nf++)
            #pragma unroll
            for (int i = 0; i < 4; i++) c[mf][nf][i] = 0.f;

    // staging indices (identical pattern to the fp32 version)
    const int a_row = tid >> 2;            // 0..63
    const int a_k4  = (tid & 3) * 4;
    const int b_col = (tid & 31) * 4;
    const int b_kr  = tid >> 5;            // 0..7
    const float* Aptr = emb + (size_t)(bm * 128) * Dz;

    float4 pa0, pa1, pb0, pb1;
    pa0 = *(const float4*)(Aptr + (size_t)a_row * Dz + a_k4);
    pa1 = *(const float4*)(Aptr + (size_t)(a_row + 64) * Dz + a_k4);
    pb0 = *(const float4*)(W + (size_t)b_kr * Gz + colb + b_col);
    pb1 = *(const float4*)(W + (size_t)(b_kr + 8) * Gz + colb + b_col);

    int p = 0;
    for (int k0 = 0; k0 < Dz; k0 += 16) {
        As[p][a_k4 + 0][a_row] = tf32r(pa0.x);
        As[p][a_k4 + 1][a_row] = tf32r(pa0.y);
        As[p][a_k4 + 2][a_row] = tf32r(pa0.z);
        As[p][a_k4 + 3][a_row] = tf32r(pa0.w);
        As[p][a_k4 + 0][a_row + 64] = tf32r(pa1.x);
        As[p][a_k4 + 1][a_row + 64] = tf32r(pa1.y);
        As[p][a_k4 + 2][a_row + 64] = tf32r(pa1.z);
        As[p][a_k4 + 3][a_row + 64] = tf32r(pa1.w);
        float4 qb0, qb1;
        qb0.x = tf32r(pb0.x); qb0.y = tf32r(pb0.y); qb0.z = tf32r(pb0.z); qb0.w = tf32r(pb0.w);
        qb1.x = tf32r(pb1.x); qb1.y = tf32r(pb1.y); qb1.z = tf32r(pb1.z); qb1.w = tf32r(pb1.w);
        *(float4*)&Bs[p][b_kr][b_col]     = qb0;
        *(float4*)&Bs[p][b_kr + 8][b_col] = qb1;
        __syncthreads();
        if (k0 + 16 < Dz) {
            int kn = k0 + 16;
            pa0 = *(const float4*)(Aptr + (size_t)a_row * Dz + kn + a_k4);
            pa1 = *(const float4*)(Aptr + (size_t)(a_row + 64) * Dz + kn + a_k4);
            pb0 = *(const float4*)(W + (size_t)(kn + b_kr) * Gz + colb + b_col);
            pb1 = *(const float4*)(W + (size_t)(kn + b_kr + 8) * Gz + colb + b_col);
        }
        // two k8 MMA steps cover BK=16
        #pragma unroll
        for (int ks = 0; ks < 16; ks += 8) {
            unsigned a[4][4], b[4][2];
            #pragma unroll
            for (int mf = 0; mf < 4; mf++) {
                const float* ap0 = &As[p][ks + tig][mb + mf * 16 + g];
                const float* ap1 = &As[p][ks + tig + 4][mb + mf * 16 + g];
                a[mf][0] = __float_as_uint(ap0[0]);
                a[mf][1] = __float_as_uint(ap0[8]);
                a[mf][2] = __float_as_uint(ap1[0]);
                a[mf][3] = __float_as_uint(ap1[8]);
            }
            #pragma unroll
            for (int nf = 0; nf < 4; nf++) {
                b[nf][0] = __float_as_uint(Bs[p][ks + tig][nb + nf * 8 + g]);
                b[nf][1] = __float_as_uint(Bs[p][ks + tig + 4][nb + nf * 8 + g]);
            }
            #pragma unroll
            for (int mf = 0; mf < 4; mf++)
                #pragma unroll
                for (int nf = 0; nf < 4; nf++)
                    mma_tf32(c[mf][nf], a[mf][0], a[mf][1], a[mf][2], a[mf][3],
                             b[nf][0], b[nf][1]);
        }
        p ^= 1;
    }

    // epilogue: c[mf][nf] -> rows (g, g+8) of frag, cols (2*tig, 2*tig+1)
    #pragma unroll
    for (int mf = 0; mf < 4; mf++) {
        #pragma unroll
        for (int nf = 0; nf < 4; nf++) {
            const int col = colb + nb + nf * 8 + tig * 2;
            const float bz0 = bias[col], bz1 = bias[col + 1];
            const int row0 = bm * 128 + mb + mf * 16 + g;
            const int row1 = row0 + 8;
            const int b0r = row0 >> 8, t0 = row0 & 255;
            const int b1r = row1 >> 8, t1 = row1 & 255;
            g_xz[dir][t0][b0r][col]     = c[mf][nf][0] + bz0;
            g_xz[dir][t0][b0r][col + 1] = c[mf][nf][1] + bz1;
            g_xz[dir][t1][b1r][col]     = c[mf][nf][2] + bz0;
            g_xz[dir][t1][b1r][col + 1] = c[mf][nf][3] + bz1;
        }
    }
}

// ---------------- persistent BiLSTM recurrence (the 3108-us configuration, frozen) ----------------
#define NCTA_DIR 64
#define UPC 8
#define HS_PAD 33
#define RED_STRIDE 40
#define SM_REC (512 * 32)                 // 16384 floats
#define SM_HS  (8 * 64 * HS_PAD)          // 16896 floats
#define SM_RED (8 * 32 * RED_STRIDE)      // 10240 floats

__global__ __launch_bounds__(256, 1) void k_lstm(
    const float* __restrict__ rf, const float* __restrict__ rb)
{
    extern __shared__ float sm[];
    float* rec_s = sm;                    // [k*32 + c]
    float* h_s   = sm + SM_REC;           // per-warp [64][HS_PAD]
    float* red   = sm + SM_REC + SM_HS;   // [w][32][RED_STRIDE]

    const int cta = blockIdx.x;
    const int dir = cta >> 6;
    const int cd  = cta & 63;
    const int u0  = cd * UPC;
    const float* __restrict__ R = dir ? rb : rf;
    const int tid = threadIdx.x;

    for (int i = tid; i < 512 * 32; i += 256) {
        int k = i >> 5, c = i & 31;
        int g = c >> 3, u = c & 7;
        rec_s[i] = R[(size_t)k * Gz + g * 512 + u0 + u];
    }

    const int w    = tid >> 5;
    const int lane = tid & 31;
    const int bb   = lane >> 2;
    const int cc   = lane & 3;
    const int b0   = bb * 4, c0 = cc * 8;
    const int kbase = w * 64;
    float* hw = h_s + w * 64 * HS_PAD;
    float* rw = red + w * 32 * RED_STRIDE;

    const int gb = tid >> 3;              // gate-phase batch 0..31
    const int gu = tid & 7;               // gate-phase unit 0..7
    float cstate = 0.f;

    const float* ghf = (const float*)g_h;

    __syncthreads();

    for (int step = 0; step < Tz; step++) {
        const int tcur = dir ? (Tz - 1 - step) : step;

        // prefetch gate pre-activations (hidden behind the fma phase)
        float zx[4];
        #pragma unroll
        for (int g = 0; g < 4; g++)
            zx[g] = g_xz[dir][tcur][gb][g * 512 + u0 + gu];

        if (step > 0) {
            const int tprev = dir ? (tcur + 1) : (tcur - 1);
            // per-warp staging of this warp's K-slice of h (transposed)
            const float* hsrc = ghf + (size_t)tprev * HCz + dir * 512 + kbase + lane * 2;
            #pragma unroll 8
            for (int bi = 0; bi < 32; bi++) {
                float2 v = *(const float2*)(hsrc + (size_t)bi * Tz * HCz);
                hw[(lane * 2) * HS_PAD + bi]     = v.x;
                hw[(lane * 2 + 1) * HS_PAD + bi] = v.y;
            }
            __syncwarp();

            unsigned long long acc[4][4];
            #pragma unroll
            for (int m = 0; m < 4; m++)
                #pragma unroll
                for (int q = 0; q < 4; q++) acc[m][q] = 0ull;

            #pragma unroll 4
            for (int kk = 0; kk < 64; kk++) {
                const float* hr = &hw[kk * HS_PAD + b0];
                float h0 = hr[0], h1 = hr[1], h2 = hr[2], h3 = hr[3];
                ulonglong2 r0 = *(const ulonglong2*)&rec_s[(kbase + kk) * 32 + c0];
                ulonglong2 r1 = *(const ulonglong2*)&rec_s[(kbase + kk) * 32 + c0 + 4];
                unsigned long long a;
                a = pk2(h0); fma2(acc[0][0], a, r0.x); fma2(acc[0][1], a, r0.y); fma2(acc[0][2], a, r1.x); fma2(acc[0][3], a, r1.y);
                a = pk2(h1); fma2(acc[1][0], a, r0.x); fma2(acc[1][1], a, r0.y); fma2(acc[1][2], a, r1.x); fma2(acc[1][3], a, r1.y);
                a = pk2(h2); fma2(acc[2][0], a, r0.x); fma2(acc[2][1], a, r0.y); fma2(acc[2][2], a, r1.x); fma2(acc[2][3], a, r1.y);
                a = pk2(h3); fma2(acc[3][0], a, r0.x); fma2(acc[3][1], a, r0.y); fma2(acc[3][2], a, r1.x); fma2(acc[3][3], a, r1.y);
            }
            #pragma unroll
            for (int m = 0; m < 4; m++) {
                #pragma unroll
                for (int q = 0; q < 4; q++) {
                    float x, y;
                    unpk(acc[m][q], x, y);
                    rw[(b0 + m) * RED_STRIDE + c0 + 2 * q]     = x;
                    rw[(b0 + m) * RED_STRIDE + c0 + 2 * q + 1] = y;
                }
            }
            __syncthreads();
        }

        // gate phase
        float z[4];
        #pragma unroll
        for (int g = 0; g < 4; g++) {
            float s = zx[g];
            if (step > 0) {
                #pragma unroll
                for (int w2 = 0; w2 < 8; w2++)
                    s += red[w2 * 32 * RED_STRIDE + gb * RED_STRIDE + g * 8 + gu];
            }
            z[g] = s;
        }
        float ig = fsig(z[0]);
        float fg = fsig(z[1]);
        float og = fsig(z[3]);
        cstate = fg * cstate + ig * ftanh(z[2]);
        float hval = og * ftanh(cstate);
        g_h[gb][tcur][dir * 512 + u0 + gu] = hval;

        __syncthreads();
        if (tid == 0) {
            __threadfence();
            atomicAdd(&g_bar[dir], 1u);
            unsigned target = (unsigned)(NCTA_DIR * (step + 1));
            while (ld_acq(&g_bar[dir]) < target) { }
        }
        __syncthreads();
    }
}

// ---------------- dense + SELU ----------------
#define DW_STRIDE 1026
#define DSM_W 25664                       // 25*1026=25650 padded to multiple of 16 floats
#define DSM_H (8 * 2048)                  // 16384 floats

__global__ __launch_bounds__(256, 1) void k_dense(
    const float* __restrict__ W, const float* __restrict__ bias,
    float* __restrict__ out, int loff)
{
    extern __shared__ float sm[];
    float* sw = sm;               // [n*DW_STRIDE + k]
    float* sh = sm + DSM_W;       // per-warp 2 rows of h (16B-aligned)

    const int tid = threadIdx.x;
    for (int i = tid; i < HCz * NCz; i += 256) {
        int k = i / NCz, n = i - k * NCz;
        sw[n * DW_STRIDE + k] = W[i];
    }
    __syncthreads();

    const int w = tid >> 5, lane = tid & 31;
    const int gw = blockIdx.x * 8 + w;     // 0..1183
    float* hh = sh + w * 2048;
    const float* ghf = (const float*)g_h;

    const float SC = 1.0507009873554804934193f;
    const float AL = 1.6732632423543772848170f;
    float bn = (lane < NCz) ? bias[lane] : 0.f;

    for (int base = gw * 2; base < Bz * Tz; base += 1184 * 2) {
        const float4* s0 = (const float4*)(ghf + (size_t)base * HCz);
        const float4* s1 = (const float4*)(ghf + (size_t)(base + 1) * HCz);
        float4* d0 = (float4*)hh;
        float4* d1 = (float4*)(hh + 1024);
        #pragma unroll
        for (int j = 0; j < 8; j++) {
            d0[j * 32 + lane] = s0[j * 32 + lane];
            d1[j * 32 + lane] = s1[j * 32 + lane];
        }
        __syncwarp();

        if (lane < NCz) {
            unsigned long long acc0 = 0ull, acc1 = 0ull;
            const float* wn = sw + lane * DW_STRIDE;
            #pragma unroll 8
            for (int k = 0; k < HCz; k += 2) {
                unsigned long long wv = *(const unsigned long long*)&wn[k];
                unsigned long long h0 = *(const unsigned long long*)&hh[k];
                unsigned long long h1 = *(const unsigned long long*)&hh[1024 + k];
                fma2(acc0, h0, wv);
                fma2(acc1, h1, wv);
            }
            float x0, y0, x1, y1;
            unpk(acc0, x0, y0);
            unpk(acc1, x1, y1);
            float v0 = x0 + y0 + bn;
            float v1 = x1 + y1 + bn;
            v0 = v0 > 0.f ? SC * v0 : SC * AL * (expf(v0) - 1.f);
            v1 = v1 > 0.f ? SC * v1 : SC * AL * (expf(v1) - 1.f);
            out[loff + (size_t)base * NCz + lane]       = v0;
            out[loff + (size_t)(base + 1) * NCz + lane] = v1;
        }
        __syncwarp();
    }
}

// ---------------- CRF NLL (one warp per batch element) ----------------
__global__ void k_crf(const float* __restrict__ logits,
                      const int* __restrict__ tags,
                      const int* __restrict__ seq_lens,
                      const float* __restrict__ trans)
{
    __shared__ float Ts[NCz * NCz];
    __shared__ float alpha[NCz];
    const int b = blockIdx.x;
    const int lane = threadIdx.x;

    for (int i = lane; i < NCz * NCz; i += 32) Ts[i] = trans[i];
    __syncwarp();

    int len = seq_lens[b];
    if (len < 1) len = 1;
    if (len > Tz) len = Tz;

    const float* __restrict__ L = logits + (size_t)b * Tz * NCz;
    const int* __restrict__ tg = tags + (size_t)b * Tz;

    float us = 0.f, bs = 0.f;
    for (int t = lane; t < len; t += 32) {
        us += L[t * NCz + tg[t]];
        if (t >= 1) bs += Ts[tg[t - 1] * NCz + tg[t]];
    }
    us = wsum(us);
    bs = wsum(bs);

    if (lane < NCz) alpha[lane] = L[lane];
    __syncwarp();
    for (int t = 1; t < len; t++) {
        float v = 0.f;
        if (lane < NCz) {
            float m = -1e30f;
            for (int i = 0; i < NCz; i++) m = fmaxf(m, alpha[i] + Ts[i * NCz + lane]);
            float s = 0.f;
            for (int i = 0; i < NCz; i++) s += expf(alpha[i] + Ts[i * NCz + lane] - m);
            v = m + logf(s) + L[t * NCz + lane];
        }
        __syncwarp();
        if (lane < NCz) alpha[lane] = v;
        __syncwarp();
    }
    float a = (lane < NCz) ? alpha[lane] : -1e30f;
    float m = wmax(a);
    float s = wsum((lane < NCz) ? expf(a - m) : 0.f);
    float logz = m + logf(s);
    if (lane == 0) g_nll[b] = -(us + bs - logz);
}

__global__ void k_loss(float* __restrict__ out, int loff) {
    float v = (threadIdx.x < Bz) ? g_nll[threadIdx.x] : 0.f;
    v = wsum(v);
    if (threadIdx.x == 0 && loff >= 1) out[0] = v / (float)Bz;
}

// ---------------- launch ----------------
extern "C" void kernel_launch(void* const* d_in, const int* in_sizes, int n_in,
                              void* d_out, int out_size)
{
    const float* emb     = (const float*)d_in[0];
    const int*   targets = (const int*)d_in[1];
    const int*   seqlens = (const int*)d_in[2];
    const float* k_fwd   = (const float*)d_in[3];
    const float* r_fwd   = (const float*)d_in[4];
    const float* b_fwd   = (const float*)d_in[5];
    const float* k_bwd   = (const float*)d_in[6];
    const float* r_bwd   = (const float*)d_in[7];
    const float* b_bwd   = (const float*)d_in[8];
    const float* dense_w = (const float*)d_in[9];
    const float* dense_b = (const float*)d_in[10];
    const float* trans   = (const float*)d_in[11];
    float* out = (float*)d_out;

    int loff = out_size - Bz * Tz * NCz;
    if (loff < 0) loff = 0;

    const int smem_lstm  = (SM_REC + SM_HS + SM_RED) * (int)sizeof(float);  // 174080
    const int smem_dense = (DSM_W + DSM_H) * (int)sizeof(float);            // 168192
    cudaFuncSetAttribute(k_lstm, cudaFuncAttributeMaxDynamicSharedMemorySize, smem_lstm);
    cudaFuncSetAttribute(k_dense, cudaFuncAttributeMaxDynamicSharedMemorySize, smem_dense);

    k_init<<<1, 1>>>();
    dim3 ggrid(32, 64);
    k_gemm_xz<<<ggrid, 256>>>(emb, k_fwd, b_fwd, k_bwd, b_bwd);
    k_pad<<<1, 32>>>();   // keeps ncu's fixed sample slot on k_lstm
    k_lstm<<<2 * NCTA_DIR, 256, smem_lstm>>>(r_fwd, r_bwd);
    k_dense<<<148, 256, smem_dense>>>(dense_w, dense_b, out, loff);
    k_crf<<<32, 32>>>(out + loff, targets, seqlens, trans);
    k_loss<<<1, 32>>>(out, loff);
}